// round 2
// baseline (speedup 1.0000x reference)
#include <cuda_runtime.h>
#include <math_constants.h>

// Reservoir2D: 1000-step Euler-Maruyama neuristor lattice + spike binning + linear readout.
// One CTA per batch sample (64 CTAs), 1024 threads = one oscillator each.

#define BATCHN 64
#define NN     1024
#define NSTEP  1000
#define NOUT   10
#define LENTB  20      // time bins
#define FEATS  (NN * LENTB)

// ---------------- JAX threefry2x32 (exact) ----------------
__device__ __forceinline__ void tf2x32(unsigned k0, unsigned k1,
                                       unsigned x0, unsigned x1,
                                       unsigned& o0, unsigned& o1) {
    unsigned k2 = k0 ^ k1 ^ 0x1BD11BDAu;
    x0 += k0; x1 += k1;
#define TF_R(r) { x0 += x1; x1 = __funnelshift_l(x1, x1, (r)); x1 ^= x0; }
    TF_R(13) TF_R(15) TF_R(26) TF_R(6)
    x0 += k1; x1 += k2 + 1u;
    TF_R(17) TF_R(29) TF_R(16) TF_R(24)
    x0 += k2; x1 += k0 + 2u;
    TF_R(13) TF_R(15) TF_R(26) TF_R(6)
    x0 += k0; x1 += k1 + 3u;
    TF_R(17) TF_R(29) TF_R(16) TF_R(24)
    x0 += k1; x1 += k2 + 4u;
    TF_R(13) TF_R(15) TF_R(26) TF_R(6)
    x0 += k2; x1 += k0 + 5u;
#undef TF_R
    o0 = x0; o1 = x1;
}

// ---------------- XLA ErfInv32 (Giles polynomial, exact coefficients) ----------------
__device__ __forceinline__ float erfinv_xla(float x) {
    float w = -log1pf(-x * x);
    float p;
    if (w < 5.0f) {
        w = w - 2.5f;
        p = 2.81022636e-08f;
        p = fmaf(p, w, 3.43273939e-07f);
        p = fmaf(p, w, -3.5233877e-06f);
        p = fmaf(p, w, -4.39150654e-06f);
        p = fmaf(p, w, 0.00021858087f);
        p = fmaf(p, w, -0.00125372503f);
        p = fmaf(p, w, -0.00417768164f);
        p = fmaf(p, w, 0.246640727f);
        p = fmaf(p, w, 1.50140941f);
    } else {
        w = sqrtf(w) - 3.0f;
        p = -0.000200214257f;
        p = fmaf(p, w, 0.000100950558f);
        p = fmaf(p, w, 0.00134934322f);
        p = fmaf(p, w, -0.00367342844f);
        p = fmaf(p, w, 0.00573950773f);
        p = fmaf(p, w, -0.0076224613f);
        p = fmaf(p, w, 0.00943887047f);
        p = fmaf(p, w, 1.00167406f);
        p = fmaf(p, w, 2.83297682f);
    }
    return p * x;
}

__global__ __launch_bounds__(1024, 1)
void Reservoir2D_kernel(const float* __restrict__ xin,
                        const float* __restrict__ W,
                        const float* __restrict__ bias,
                        float* __restrict__ out) {
    __shared__ float Tsh[NN];
    __shared__ uint2 keys[NSTEP];          // per-step threefry keys (fold-like split of key(1))
    __shared__ float red[32 * NOUT];

    const int n = threadIdx.x;
    const int b = blockIdx.x;

    // keys[t] = threefry2x32(key=(0,1), counter=(0,t))  [partitionable fold-like split]
    if (n < NSTEP) {
        unsigned o0, o1;
        tf2x32(0u, 1u, 0u, (unsigned)n, o0, o1);
        keys[n] = make_uint2(o0, o1);
    }

    // grid neighbors with wraparound (n = i*32 + j)
    const int i = n >> 5, j = n & 31;
    const int xm = (((i + 31) & 31) << 5) | j;
    const int xp = (((i + 1)  & 31) << 5) | j;
    const int ym = (i << 5) | ((j + 31) & 31);
    const int yp = (i << 5) | ((j + 1)  & 31);

    const float Vd = 11.0f + 2.0f * xin[b * NN + n];
    float v = 0.0f;
    float T = 325.0f;
    float prevI = CUDART_INF_F;
    int   cd = 0;
    unsigned mask = 0;
    const unsigned e = (unsigned)(b * NN + n);   // element index in (batch, N) row-major

    const float LOG_R_INS = 4.6051702499389648f;      // f32(log(100))
    const float U_LO      = -0.99999994039535522461f; // nextafter(-1,0)
    const float SQRT2     = 1.41421353816986083984f;  // f32(sqrt(2))
    const float NSCALE    = 0.001f * 3.1622776985168457f; // NOISE*sqrt(DT), f32-folded

    __syncthreads();   // keys visible

    for (int t = 0; t < NSTEP; ++t) {
        Tsh[n] = T;
        __syncthreads();
        float lap = ((Tsh[xm] + Tsh[xp]) + Tsh[ym]) + Tsh[yp] - 4.0f * T;
        __syncthreads();

        // ---- noise: JAX partitionable random_bits -> uniform(lo,1) -> sqrt(2)*erfinv ----
        uint2 kk = keys[t];
        unsigned o0, o1;
        tf2x32(kk.x, kk.y, 0u, e, o0, o1);
        unsigned bits = o0 ^ o1;
        float f  = __uint_as_float((bits >> 9) | 0x3F800000u) - 1.0f;  // [0,1)
        float u  = f * 2.0f + U_LO;                                    // (hi-lo) rounds to 2.0f
        u = fmaxf(u, U_LO);
        float noise = NSCALE * (SQRT2 * erfinv_xla(u));

        // ---- device model ----
        float xs = (T - 340.0f) / 5.0f;
        float s  = 1.0f / (1.0f + expf(-xs));
        float a  = (1.0f - s) * LOG_R_INS + s * 0.0f;
        float G  = expf(-a);
        float I  = v * G;

        float vn = v + (10.0f * ((Vd - v) / 12.0f - I)) / 100.0f;
        float q  = (v * I - (T - 325.0f)) + 0.02f * lap;
        float Tn = (T + (10.0f * q) / 1000.0f) + noise;

        // ---- rising-edge peak detection with refractory 101 ----
        bool pk = (I > 1.5f) && (prevI <= 1.5f) && (cd <= 0);
        if (pk) { mask |= 1u << (t / 50); cd = 101; }
        else    { cd -= 1; }

        prevI = I; v = vn; T = Tn;
    }

    // ---- readout: logits[o] = sum_n sum_tb count * W[o, n*20+tb] ----
    float acc[NOUT];
#pragma unroll
    for (int o = 0; o < NOUT; ++o) acc[o] = 0.0f;

#pragma unroll
    for (int tb = 0; tb < LENTB; ++tb) {
        if ((mask >> tb) & 1u) {
            const float* wp = W + (n * LENTB + tb);
#pragma unroll
            for (int o = 0; o < NOUT; ++o) acc[o] += wp[o * FEATS];
        }
    }

    // deterministic reduction: warp shuffle then cross-warp
#pragma unroll
    for (int o = 0; o < NOUT; ++o) {
        float a2 = acc[o];
#pragma unroll
        for (int sft = 16; sft > 0; sft >>= 1)
            a2 += __shfl_xor_sync(0xFFFFFFFFu, a2, sft);
        acc[o] = a2;
    }
    const int wid = n >> 5;
    if ((n & 31) == 0) {
#pragma unroll
        for (int o = 0; o < NOUT; ++o) red[wid * NOUT + o] = acc[o];
    }
    __syncthreads();

    if (n == 0) {
        float lg[NOUT];
#pragma unroll
        for (int o = 0; o < NOUT; ++o) {
            float sacc = bias[o];
            for (int w = 0; w < 32; ++w) sacc += red[w * NOUT + o];
            lg[o] = sacc;
        }
        float m = lg[0];
#pragma unroll
        for (int o = 1; o < NOUT; ++o) m = fmaxf(m, lg[o]);
        float se = 0.0f;
#pragma unroll
        for (int o = 0; o < NOUT; ++o) se += expf(lg[o] - m);
        float lse = logf(se);
#pragma unroll
        for (int o = 0; o < NOUT; ++o) out[b * NOUT + o] = (lg[o] - m) - lse;
    }
}

extern "C" void kernel_launch(void* const* d_in, const int* in_sizes, int n_in,
                              void* d_out, int out_size) {
    const float* x    = (const float*)d_in[0];
    const float* W    = (const float*)d_in[1];
    const float* bias = (const float*)d_in[2];
    float* out = (float*)d_out;
    Reservoir2D_kernel<<<BATCHN, NN>>>(x, W, bias, out);
}

// round 3
// speedup vs baseline: 2.0133x; 2.0133x over previous
#include <cuda_runtime.h>
#include <math_constants.h>

// Reservoir2D: noise hoisted out of the sequential loop.
// Persistent co-scheduled kernel: CTAs [0,64) run the 1000-step sim (1 thread
// per oscillator), CTAs [64,148) produce the threefry/erfinv noise stream into
// a device buffer in 25-step chunks, release/acquire-synced with the sim.

#define BATCHN 64
#define NN     1024
#define NSTEP  1000
#define NOUT   10
#define LENTB  20
#define FEATS  (NN * LENTB)
#define ETOT   (BATCHN * NN)        // 65536 elements per step
#define CHSTEP 25                   // steps per noise chunk
#define NCHUNK (NSTEP / CHSTEP)     // 40 chunks
#define NOISE_CTAS 84
#define TOTAL_CTAS (BATCHN + NOISE_CTAS)

__device__ float    g_noise[NSTEP * ETOT];   // 262 MB scratch (allowed: __device__ global)
__device__ unsigned g_cnt[64];               // per-chunk completion counters

// ---------------- JAX threefry2x32 (exact) ----------------
__device__ __forceinline__ void tf2x32(unsigned k0, unsigned k1,
                                       unsigned x0, unsigned x1,
                                       unsigned& o0, unsigned& o1) {
    unsigned k2 = k0 ^ k1 ^ 0x1BD11BDAu;
    x0 += k0; x1 += k1;
#define TF_R(r) { x0 += x1; x1 = __funnelshift_l(x1, x1, (r)); x1 ^= x0; }
    TF_R(13) TF_R(15) TF_R(26) TF_R(6)
    x0 += k1; x1 += k2 + 1u;
    TF_R(17) TF_R(29) TF_R(16) TF_R(24)
    x0 += k2; x1 += k0 + 2u;
    TF_R(13) TF_R(15) TF_R(26) TF_R(6)
    x0 += k0; x1 += k1 + 3u;
    TF_R(17) TF_R(29) TF_R(16) TF_R(24)
    x0 += k1; x1 += k2 + 4u;
    TF_R(13) TF_R(15) TF_R(26) TF_R(6)
    x0 += k2; x1 += k0 + 5u;
#undef TF_R
    o0 = x0; o1 = x1;
}

// ---------------- XLA ErfInv32 (Giles polynomial, exact coefficients) ----------------
__device__ __forceinline__ float erfinv_xla(float x) {
    float w = -log1pf(-x * x);
    float p;
    if (w < 5.0f) {
        w = w - 2.5f;
        p = 2.81022636e-08f;
        p = fmaf(p, w, 3.43273939e-07f);
        p = fmaf(p, w, -3.5233877e-06f);
        p = fmaf(p, w, -4.39150654e-06f);
        p = fmaf(p, w, 0.00021858087f);
        p = fmaf(p, w, -0.00125372503f);
        p = fmaf(p, w, -0.00417768164f);
        p = fmaf(p, w, 0.246640727f);
        p = fmaf(p, w, 1.50140941f);
    } else {
        w = sqrtf(w) - 3.0f;
        p = -0.000200214257f;
        p = fmaf(p, w, 0.000100950558f);
        p = fmaf(p, w, 0.00134934322f);
        p = fmaf(p, w, -0.00367342844f);
        p = fmaf(p, w, 0.00573950773f);
        p = fmaf(p, w, -0.0076224613f);
        p = fmaf(p, w, 0.00943887047f);
        p = fmaf(p, w, 1.00167406f);
        p = fmaf(p, w, 2.83297682f);
    }
    return p * x;
}

__device__ __forceinline__ float noise_val(unsigned k0, unsigned k1, unsigned e) {
    const float U_LO   = -0.99999994039535522461f;
    const float SQRT2  = 1.41421353816986083984f;
    const float NSCALE = 0.001f * 3.1622776985168457f;
    unsigned o0, o1;
    tf2x32(k0, k1, 0u, e, o0, o1);
    unsigned bits = o0 ^ o1;
    float f = __uint_as_float((bits >> 9) | 0x3F800000u) - 1.0f;
    float u = fmaxf(f * 2.0f + U_LO, U_LO);
    return NSCALE * (SQRT2 * erfinv_xla(u));
}

__device__ __forceinline__ unsigned ld_acq(const unsigned* p) {
    unsigned v;
    asm volatile("ld.acquire.gpu.global.b32 %0, [%1];" : "=r"(v) : "l"(p));
    return v;
}

__global__ void reset_cnt_kernel() {
    if (threadIdx.x < 64) g_cnt[threadIdx.x] = 0u;
}

__global__ __launch_bounds__(1024, 1)
void Reservoir2D_kernel(const float* __restrict__ xin,
                        const float* __restrict__ W,
                        const float* __restrict__ bias,
                        float* __restrict__ out) {
    __shared__ float Tsh[2][NN];
    __shared__ float red[32 * NOUT];
    __shared__ uint2 keys[NSTEP];   // used by noise CTAs only

    const int n = threadIdx.x;
    const int b = blockIdx.x;

    if (b >= BATCHN) {
        // ======================= NOISE PRODUCER =======================
        const int rk = b - BATCHN;
        if (n < NSTEP) {
            unsigned o0, o1;
            tf2x32(0u, 1u, 0u, (unsigned)n, o0, o1);   // fold-like split of key(1)
            keys[n] = make_uint2(o0, o1);
        }
        __syncthreads();

        const int chunkElems = CHSTEP * ETOT;
        for (int c = 0; c < NCHUNK; ++c) {
            const int base = c * chunkElems;
            for (int idx = rk * NN + n; idx < chunkElems; idx += NOISE_CTAS * NN) {
                int gi = base + idx;
                int t  = gi >> 16;            // ETOT == 2^16
                unsigned e = (unsigned)(gi & (ETOT - 1));
                uint2 kk = keys[t];
                g_noise[gi] = noise_val(kk.x, kk.y, e);
            }
            __syncthreads();
            if (n == 0) {
                __threadfence();
                atomicAdd(&g_cnt[c], 1u);
            }
        }
        return;
    }

    // =========================== SIMULATION ===========================
    const int i = n >> 5, j = n & 31;
    const int xm = (((i + 31) & 31) << 5) | j;
    const int xp = (((i + 1)  & 31) << 5) | j;
    const int ym = (i << 5) | ((j + 31) & 31);
    const int yp = (i << 5) | ((j + 1)  & 31);

    const float Vd = 11.0f + 2.0f * xin[b * NN + n];
    float v = 0.0f;
    float T = 325.0f;
    float prevI = CUDART_INF_F;
    int   cd = 0;
    unsigned mask = 0;
    const int e = b * NN + n;

    const float LOG_R_INS = 4.6051702499389648f;   // f32(log(100))

    // wait for chunk 0, preload noise for t=0
    if (n == 0) { while (ld_acq(&g_cnt[0]) < NOISE_CTAS) __nanosleep(64); }
    __syncthreads();
    float nz = __ldg(&g_noise[e]);

    int p = 0;
    for (int t = 0; t < NSTEP; ++t) {
        Tsh[p][n] = T;

        const int tn = t + 1;
        if (tn < NSTEP && (tn % CHSTEP) == 0) {     // chunk boundary: 39 times total
            const int c = tn / CHSTEP;
            if (n == 0) { while (ld_acq(&g_cnt[c]) < NOISE_CTAS) __nanosleep(64); }
            __syncthreads();
        }
        float nz_next = (tn < NSTEP) ? __ldg(&g_noise[tn * ETOT + e]) : 0.0f;

        __syncthreads();
        float lap = ((Tsh[p][xm] + Tsh[p][xp]) + Tsh[p][ym]) + Tsh[p][yp] - 4.0f * T;

        // ---- device model (exact op order, bit-identical to reference) ----
        float xs = (T - 340.0f) / 5.0f;
        float s  = 1.0f / (1.0f + expf(-xs));
        float a  = (1.0f - s) * LOG_R_INS + s * 0.0f;
        float G  = expf(-a);
        float I  = v * G;

        float vn = v + (10.0f * ((Vd - v) / 12.0f - I)) / 100.0f;
        float q  = (v * I - (T - 325.0f)) + 0.02f * lap;
        float Tn = (T + (10.0f * q) / 1000.0f) + nz;

        // ---- rising-edge peak detection, refractory 101 ----
        bool pk = (I > 1.5f) && (prevI <= 1.5f) && (cd <= 0);
        if (pk) { mask |= 1u << (t / 50); cd = 101; }
        else    { cd -= 1; }

        prevI = I; v = vn; T = Tn;
        nz = nz_next; p ^= 1;
    }

    // ---- readout ----
    float acc[NOUT];
#pragma unroll
    for (int o = 0; o < NOUT; ++o) acc[o] = 0.0f;
#pragma unroll
    for (int tb = 0; tb < LENTB; ++tb) {
        if ((mask >> tb) & 1u) {
            const float* wp = W + (n * LENTB + tb);
#pragma unroll
            for (int o = 0; o < NOUT; ++o) acc[o] += wp[o * FEATS];
        }
    }
#pragma unroll
    for (int o = 0; o < NOUT; ++o) {
        float a2 = acc[o];
#pragma unroll
        for (int sft = 16; sft > 0; sft >>= 1)
            a2 += __shfl_xor_sync(0xFFFFFFFFu, a2, sft);
        acc[o] = a2;
    }
    const int wid = n >> 5;
    if ((n & 31) == 0) {
#pragma unroll
        for (int o = 0; o < NOUT; ++o) red[wid * NOUT + o] = acc[o];
    }
    __syncthreads();

    if (n == 0) {
        float lg[NOUT];
#pragma unroll
        for (int o = 0; o < NOUT; ++o) {
            float sacc = bias[o];
            for (int w = 0; w < 32; ++w) sacc += red[w * NOUT + o];
            lg[o] = sacc;
        }
        float m = lg[0];
#pragma unroll
        for (int o = 1; o < NOUT; ++o) m = fmaxf(m, lg[o]);
        float se = 0.0f;
#pragma unroll
        for (int o = 0; o < NOUT; ++o) se += expf(lg[o] - m);
        float lse = logf(se);
#pragma unroll
        for (int o = 0; o < NOUT; ++o) out[b * NOUT + o] = (lg[o] - m) - lse;
    }
}

extern "C" void kernel_launch(void* const* d_in, const int* in_sizes, int n_in,
                              void* d_out, int out_size) {
    const float* x    = (const float*)d_in[0];
    const float* W    = (const float*)d_in[1];
    const float* bias = (const float*)d_in[2];
    float* out = (float*)d_out;
    reset_cnt_kernel<<<1, 64>>>();
    Reservoir2D_kernel<<<TOTAL_CTAS, NN>>>(x, W, bias, out);
}

// round 4
// speedup vs baseline: 2.0194x; 1.0030x over previous
#include <cuda_runtime.h>
#include <math_constants.h>

// Reservoir2D: noise hoisted to producer CTAs + bit-exact 2-FMA constant division.
// CTAs [0,64) sim (1 thread/oscillator), CTAs [64,148) produce threefry/erfinv
// noise into a device ring, release/acquire-synced in 25-step chunks.

#define BATCHN 64
#define NN     1024
#define NSTEP  1000
#define NOUT   10
#define LENTB  20
#define FEATS  (NN * LENTB)
#define ETOT   (BATCHN * NN)        // 65536 elements per step
#define CHSTEP 25
#define NCHUNK (NSTEP / CHSTEP)     // 40
#define NOISE_CTAS 84
#define TOTAL_CTAS (BATCHN + NOISE_CTAS)

__device__ float    g_noise[NSTEP * ETOT];   // 262 MB scratch
__device__ unsigned g_cnt[64];

// ---- bit-exact division by small integer constant: q = fma(x,c1, x*c2) ----
// c1 = RN(1/d), c2 = RN(1/d - c1). Correctly rounded for d in {5,12,100,1000}:
// x/d can never be an f32 rounding midpoint (d*J, J odd 25-bit, exceeds 24-bit
// mantissa), margin >= ~2^-31 rel, scheme error <= ~2^-48 rel.
__device__ __forceinline__ float divc(float x, float c1, float c2) {
    return fmaf(x, c1, x * c2);
}
#define DC(d) (float)(1.0/(d)), (float)(1.0/(d) - (double)(float)(1.0/(d)))

// ---------------- JAX threefry2x32 (exact) ----------------
__device__ __forceinline__ void tf2x32(unsigned k0, unsigned k1,
                                       unsigned x0, unsigned x1,
                                       unsigned& o0, unsigned& o1) {
    unsigned k2 = k0 ^ k1 ^ 0x1BD11BDAu;
    x0 += k0; x1 += k1;
#define TF_R(r) { x0 += x1; x1 = __funnelshift_l(x1, x1, (r)); x1 ^= x0; }
    TF_R(13) TF_R(15) TF_R(26) TF_R(6)
    x0 += k1; x1 += k2 + 1u;
    TF_R(17) TF_R(29) TF_R(16) TF_R(24)
    x0 += k2; x1 += k0 + 2u;
    TF_R(13) TF_R(15) TF_R(26) TF_R(6)
    x0 += k0; x1 += k1 + 3u;
    TF_R(17) TF_R(29) TF_R(16) TF_R(24)
    x0 += k1; x1 += k2 + 4u;
    TF_R(13) TF_R(15) TF_R(26) TF_R(6)
    x0 += k2; x1 += k0 + 5u;
#undef TF_R
    o0 = x0; o1 = x1;
}

// ---------------- XLA ErfInv32 (Giles polynomial, exact) ----------------
__device__ __forceinline__ float erfinv_xla(float x) {
    float w = -log1pf(-x * x);
    float p;
    if (w < 5.0f) {
        w = w - 2.5f;
        p = 2.81022636e-08f;
        p = fmaf(p, w, 3.43273939e-07f);
        p = fmaf(p, w, -3.5233877e-06f);
        p = fmaf(p, w, -4.39150654e-06f);
        p = fmaf(p, w, 0.00021858087f);
        p = fmaf(p, w, -0.00125372503f);
        p = fmaf(p, w, -0.00417768164f);
        p = fmaf(p, w, 0.246640727f);
        p = fmaf(p, w, 1.50140941f);
    } else {
        w = sqrtf(w) - 3.0f;
        p = -0.000200214257f;
        p = fmaf(p, w, 0.000100950558f);
        p = fmaf(p, w, 0.00134934322f);
        p = fmaf(p, w, -0.00367342844f);
        p = fmaf(p, w, 0.00573950773f);
        p = fmaf(p, w, -0.0076224613f);
        p = fmaf(p, w, 0.00943887047f);
        p = fmaf(p, w, 1.00167406f);
        p = fmaf(p, w, 2.83297682f);
    }
    return p * x;
}

__device__ __forceinline__ float noise_val(unsigned k0, unsigned k1, unsigned e) {
    const float U_LO   = -0.99999994039535522461f;
    const float SQRT2  = 1.41421353816986083984f;
    const float NSCALE = 0.001f * 3.1622776985168457f;
    unsigned o0, o1;
    tf2x32(k0, k1, 0u, e, o0, o1);
    unsigned bits = o0 ^ o1;
    float f = __uint_as_float((bits >> 9) | 0x3F800000u) - 1.0f;
    float u = fmaxf(f * 2.0f + U_LO, U_LO);
    return NSCALE * (SQRT2 * erfinv_xla(u));
}

__device__ __forceinline__ unsigned ld_acq(const unsigned* p) {
    unsigned v;
    asm volatile("ld.acquire.gpu.global.b32 %0, [%1];" : "=r"(v) : "l"(p));
    return v;
}

__global__ void reset_cnt_kernel() {
    if (threadIdx.x < 64) g_cnt[threadIdx.x] = 0u;
}

__global__ __launch_bounds__(1024, 1)
void Reservoir2D_kernel(const float* __restrict__ xin,
                        const float* __restrict__ W,
                        const float* __restrict__ bias,
                        float* __restrict__ out) {
    __shared__ float Tsh[2][NN];
    __shared__ float red[32 * NOUT];
    __shared__ uint2 keys[NSTEP];   // producers only

    const int n = threadIdx.x;
    const int b = blockIdx.x;

    if (b >= BATCHN) {
        // ======================= NOISE PRODUCER =======================
        const int rk = b - BATCHN;
        if (n < NSTEP) {
            unsigned o0, o1;
            tf2x32(0u, 1u, 0u, (unsigned)n, o0, o1);   // fold-like split of key(1)
            keys[n] = make_uint2(o0, o1);
        }
        __syncthreads();

        const int chunkElems = CHSTEP * ETOT;
        for (int c = 0; c < NCHUNK; ++c) {
            const int base = c * chunkElems;
            for (int idx = rk * NN + n; idx < chunkElems; idx += NOISE_CTAS * NN) {
                int gi = base + idx;
                int t  = gi >> 16;            // ETOT == 2^16
                unsigned e = (unsigned)(gi & (ETOT - 1));
                uint2 kk = keys[t];
                g_noise[gi] = noise_val(kk.x, kk.y, e);
            }
            __syncthreads();
            if (n == 0) {
                __threadfence();
                atomicAdd(&g_cnt[c], 1u);
            }
        }
        return;
    }

    // =========================== SIMULATION ===========================
    const int i = n >> 5, j = n & 31;
    const int xm = (((i + 31) & 31) << 5) | j;
    const int xp = (((i + 1)  & 31) << 5) | j;
    const int ym = (i << 5) | ((j + 31) & 31);
    const int yp = (i << 5) | ((j + 1)  & 31);

    const float Vd = 11.0f + 2.0f * xin[b * NN + n];
    float v = 0.0f;
    float T = 325.0f;
    float prevI = CUDART_INF_F;
    int   cd = 0;
    unsigned mask = 0;
    unsigned binbit = 1u;
    int c50 = 50;
    const int e = b * NN + n;

    const float LOG_R_INS = 4.6051702499389648f;   // f32(log(100))

    if (n == 0) { while (ld_acq(&g_cnt[0]) < NOISE_CTAS) __nanosleep(64); }
    __syncthreads();
    float nz = __ldg(&g_noise[e]);

    int p = 0;
    for (int t = 0; t < NSTEP; ++t) {
        Tsh[p][n] = T;

        const int tn = t + 1;
        if (tn < NSTEP && (tn % CHSTEP) == 0) {
            const int c = tn / CHSTEP;
            if (n == 0) { while (ld_acq(&g_cnt[c]) < NOISE_CTAS) __nanosleep(64); }
            __syncthreads();
        }
        float nz_next = (tn < NSTEP) ? __ldg(&g_noise[tn * ETOT + e]) : 0.0f;

        __syncthreads();
        float lap = ((Tsh[p][xm] + Tsh[p][xp]) + Tsh[p][ym]) + Tsh[p][yp] - 4.0f * T;

        // ---- device model (bit-identical; constant divides via 2-FMA) ----
        float xs = divc(T - 340.0f, DC(5.0));
        float s  = 1.0f / (1.0f + expf(-xs));
        float a  = (1.0f - s) * LOG_R_INS;          // + s*0.0f == +0, a>=0 -> exact
        float G  = expf(-a);
        float I  = v * G;

        float vn = v + divc(10.0f * (divc(Vd - v, DC(12.0)) - I), DC(100.0));
        float q  = (v * I - (T - 325.0f)) + 0.02f * lap;
        float Tn = (T + divc(10.0f * q, DC(1000.0))) + nz;

        // ---- rising-edge peak detection, refractory 101 ----
        bool pk = (I > 1.5f) && (prevI <= 1.5f) && (cd <= 0);
        if (pk) { mask |= binbit; cd = 101; }
        else    { cd -= 1; }
        if (--c50 == 0) { c50 = 50; binbit <<= 1; }

        prevI = I; v = vn; T = Tn;
        nz = nz_next; p ^= 1;
    }

    // ---- readout ----
    float acc[NOUT];
#pragma unroll
    for (int o = 0; o < NOUT; ++o) acc[o] = 0.0f;
#pragma unroll
    for (int tb = 0; tb < LENTB; ++tb) {
        if ((mask >> tb) & 1u) {
            const float* wp = W + (n * LENTB + tb);
#pragma unroll
            for (int o = 0; o < NOUT; ++o) acc[o] += wp[o * FEATS];
        }
    }
#pragma unroll
    for (int o = 0; o < NOUT; ++o) {
        float a2 = acc[o];
#pragma unroll
        for (int sft = 16; sft > 0; sft >>= 1)
            a2 += __shfl_xor_sync(0xFFFFFFFFu, a2, sft);
        acc[o] = a2;
    }
    const int wid = n >> 5;
    if ((n & 31) == 0) {
#pragma unroll
        for (int o = 0; o < NOUT; ++o) red[wid * NOUT + o] = acc[o];
    }
    __syncthreads();

    if (n == 0) {
        float lg[NOUT];
#pragma unroll
        for (int o = 0; o < NOUT; ++o) {
            float sacc = bias[o];
            for (int w = 0; w < 32; ++w) sacc += red[w * NOUT + o];
            lg[o] = sacc;
        }
        float m = lg[0];
#pragma unroll
        for (int o = 1; o < NOUT; ++o) m = fmaxf(m, lg[o]);
        float se = 0.0f;
#pragma unroll
        for (int o = 0; o < NOUT; ++o) se += expf(lg[o] - m);
        float lse = logf(se);
#pragma unroll
        for (int o = 0; o < NOUT; ++o) out[b * NOUT + o] = (lg[o] - m) - lse;
    }
}

extern "C" void kernel_launch(void* const* d_in, const int* in_sizes, int n_in,
                              void* d_out, int out_size) {
    const float* x    = (const float*)d_in[0];
    const float* W    = (const float*)d_in[1];
    const float* bias = (const float*)d_in[2];
    float* out = (float*)d_out;
    reset_cnt_kernel<<<1, 64>>>();
    Reservoir2D_kernel<<<TOTAL_CTAS, NN>>>(x, W, bias, out);
}

// round 5
// speedup vs baseline: 2.0704x; 1.0253x over previous
#include <cuda_runtime.h>
#include <math_constants.h>

// Reservoir2D: producer/consumer persistent kernel.
// CTAs [0,64): 1000-step sim, 1 thread/oscillator.
// CTAs [64,148): threefry/erfinv noise producers, ILP-2 (element pairs),
//                paired key-schedule + STG.64, 25-step chunks, release/acquire.

#define BATCHN 64
#define NN     1024
#define NSTEP  1000
#define NOUT   10
#define LENTB  20
#define FEATS  (NN * LENTB)
#define ETOT   (BATCHN * NN)        // 65536 per step
#define CHSTEP 25
#define NCHUNK (NSTEP / CHSTEP)     // 40
#define NOISE_CTAS 84
#define TOTAL_CTAS (BATCHN + NOISE_CTAS)

__device__ float    g_noise[NSTEP * ETOT];   // 262 MB scratch
__device__ unsigned g_cnt[64];

// ---- bit-exact division by small integer constant: q = fma(x,c1, x*c2) ----
__device__ __forceinline__ float divc(float x, float c1, float c2) {
    return fmaf(x, c1, x * c2);
}
#define DC(d) (float)(1.0/(d)), (float)(1.0/(d) - (double)(float)(1.0/(d)))

// ---------------- JAX threefry2x32 (exact) ----------------
__device__ __forceinline__ void tf2x32(unsigned k0, unsigned k1,
                                       unsigned x0, unsigned x1,
                                       unsigned& o0, unsigned& o1) {
    unsigned k2 = k0 ^ k1 ^ 0x1BD11BDAu;
    x0 += k0; x1 += k1;
#define TF_R(r) { x0 += x1; x1 = __funnelshift_l(x1, x1, (r)); x1 ^= x0; }
    TF_R(13) TF_R(15) TF_R(26) TF_R(6)
    x0 += k1; x1 += k2 + 1u;
    TF_R(17) TF_R(29) TF_R(16) TF_R(24)
    x0 += k2; x1 += k0 + 2u;
    TF_R(13) TF_R(15) TF_R(26) TF_R(6)
    x0 += k0; x1 += k1 + 3u;
    TF_R(17) TF_R(29) TF_R(16) TF_R(24)
    x0 += k1; x1 += k2 + 4u;
    TF_R(13) TF_R(15) TF_R(26) TF_R(6)
    x0 += k2; x1 += k0 + 5u;
#undef TF_R
    o0 = x0; o1 = x1;
}

// ---------------- XLA ErfInv32 (Giles polynomial, exact) ----------------
__device__ __forceinline__ float erfinv_xla(float x) {
    float w = -log1pf(-x * x);
    float p;
    if (w < 5.0f) {
        w = w - 2.5f;
        p = 2.81022636e-08f;
        p = fmaf(p, w, 3.43273939e-07f);
        p = fmaf(p, w, -3.5233877e-06f);
        p = fmaf(p, w, -4.39150654e-06f);
        p = fmaf(p, w, 0.00021858087f);
        p = fmaf(p, w, -0.00125372503f);
        p = fmaf(p, w, -0.00417768164f);
        p = fmaf(p, w, 0.246640727f);
        p = fmaf(p, w, 1.50140941f);
    } else {
        w = sqrtf(w) - 3.0f;
        p = -0.000200214257f;
        p = fmaf(p, w, 0.000100950558f);
        p = fmaf(p, w, 0.00134934322f);
        p = fmaf(p, w, -0.00367342844f);
        p = fmaf(p, w, 0.00573950773f);
        p = fmaf(p, w, -0.0076224613f);
        p = fmaf(p, w, 0.00943887047f);
        p = fmaf(p, w, 1.00167406f);
        p = fmaf(p, w, 2.83297682f);
    }
    return p * x;
}

// Pair of noise values for elements (e0, e0+1), same step key. Threefry chains
// hand-interleaved for ILP-2; identical per-lane arithmetic to tf2x32.
__device__ __forceinline__ float2 noise_pair(unsigned k0, unsigned k1, unsigned e0) {
    const float U_LO   = -0.99999994039535522461f;
    const float SQRT2  = 1.41421353816986083984f;
    const float NSCALE = 0.001f * 3.1622776985168457f;

    unsigned k2 = k0 ^ k1 ^ 0x1BD11BDAu;
    unsigned xa0 = k0,       xa1 = e0 + k1;
    unsigned xb0 = k0,       xb1 = (e0 + 1u) + k1;
#define RND2(r) { xa0 += xa1; xb0 += xb1; \
                  xa1 = __funnelshift_l(xa1, xa1, (r)); \
                  xb1 = __funnelshift_l(xb1, xb1, (r)); \
                  xa1 ^= xa0; xb1 ^= xb0; }
    RND2(13) RND2(15) RND2(26) RND2(6)
    xa0 += k1; xb0 += k1; xa1 += k2 + 1u; xb1 += k2 + 1u;
    RND2(17) RND2(29) RND2(16) RND2(24)
    xa0 += k2; xb0 += k2; xa1 += k0 + 2u; xb1 += k0 + 2u;
    RND2(13) RND2(15) RND2(26) RND2(6)
    xa0 += k0; xb0 += k0; xa1 += k1 + 3u; xb1 += k1 + 3u;
    RND2(17) RND2(29) RND2(16) RND2(24)
    xa0 += k1; xb0 += k1; xa1 += k2 + 4u; xb1 += k2 + 4u;
    RND2(13) RND2(15) RND2(26) RND2(6)
    xa0 += k2; xb0 += k2; xa1 += k0 + 5u; xb1 += k0 + 5u;
#undef RND2
    unsigned ba = xa0 ^ xa1;
    unsigned bb = xb0 ^ xb1;

    float fa = __uint_as_float((ba >> 9) | 0x3F800000u) - 1.0f;
    float fb = __uint_as_float((bb >> 9) | 0x3F800000u) - 1.0f;
    float ua = fmaxf(fa * 2.0f + U_LO, U_LO);
    float ub = fmaxf(fb * 2.0f + U_LO, U_LO);

    float2 r;
    r.x = NSCALE * (SQRT2 * erfinv_xla(ua));
    r.y = NSCALE * (SQRT2 * erfinv_xla(ub));
    return r;
}

__device__ __forceinline__ unsigned ld_acq(const unsigned* p) {
    unsigned v;
    asm volatile("ld.acquire.gpu.global.b32 %0, [%1];" : "=r"(v) : "l"(p));
    return v;
}

__global__ void reset_cnt_kernel() {
    if (threadIdx.x < 64) g_cnt[threadIdx.x] = 0u;
}

__global__ __launch_bounds__(1024, 1)
void Reservoir2D_kernel(const float* __restrict__ xin,
                        const float* __restrict__ W,
                        const float* __restrict__ bias,
                        float* __restrict__ out) {
    __shared__ float Tsh[2][NN];
    __shared__ float red[32 * NOUT];
    __shared__ uint2 keys[NSTEP];   // producers only

    const int n = threadIdx.x;
    const int b = blockIdx.x;

    if (b >= BATCHN) {
        // ======================= NOISE PRODUCER (ILP-2) =======================
        const int rk = b - BATCHN;
        if (n < NSTEP) {
            unsigned o0, o1;
            tf2x32(0u, 1u, 0u, (unsigned)n, o0, o1);   // fold-like split of key(1)
            keys[n] = make_uint2(o0, o1);
        }
        __syncthreads();

        const int pairsPerChunk = (CHSTEP * ETOT) / 2;   // 819200
        float2* __restrict__ g2 = reinterpret_cast<float2*>(g_noise);
        for (int c = 0; c < NCHUNK; ++c) {
            const int pbase = c * pairsPerChunk;
            for (int pi = rk * NN + n; pi < pairsPerChunk; pi += NOISE_CTAS * NN) {
                int gp = pbase + pi;                 // pair index; element g0 = 2*gp (even)
                int t  = gp >> 15;                   // (2*gp) >> 16
                unsigned e0 = (unsigned)((gp << 1) & (ETOT - 1));  // same t for e0,e0+1
                uint2 kk = keys[t];
                g2[gp] = noise_pair(kk.x, kk.y, e0);
            }
            __syncthreads();
            if (n == 0) {
                __threadfence();
                atomicAdd(&g_cnt[c], 1u);
            }
        }
        return;
    }

    // =========================== SIMULATION ===========================
    const int i = n >> 5, j = n & 31;
    const int xm = (((i + 31) & 31) << 5) | j;
    const int xp = (((i + 1)  & 31) << 5) | j;
    const int ym = (i << 5) | ((j + 31) & 31);
    const int yp = (i << 5) | ((j + 1)  & 31);

    const float Vd = 11.0f + 2.0f * xin[b * NN + n];
    float v = 0.0f;
    float T = 325.0f;
    float prevI = CUDART_INF_F;
    int   cd = 0;
    unsigned mask = 0;
    unsigned binbit = 1u;
    int c50 = 50;
    const int e = b * NN + n;

    const float LOG_R_INS = 4.6051702499389648f;   // f32(log(100))

    if (n == 0) { while (ld_acq(&g_cnt[0]) < NOISE_CTAS) __nanosleep(64); }
    __syncthreads();
    float nz = __ldg(&g_noise[e]);

    int p = 0;
    for (int t = 0; t < NSTEP; ++t) {
        Tsh[p][n] = T;

        const int tn = t + 1;
        if (tn < NSTEP && (tn % CHSTEP) == 0) {
            const int c = tn / CHSTEP;
            if (n == 0) { while (ld_acq(&g_cnt[c]) < NOISE_CTAS) __nanosleep(64); }
            __syncthreads();
        }
        float nz_next = (tn < NSTEP) ? __ldg(&g_noise[tn * ETOT + e]) : 0.0f;

        __syncthreads();
        float lap = ((Tsh[p][xm] + Tsh[p][xp]) + Tsh[p][ym]) + Tsh[p][yp] - 4.0f * T;

        // ---- device model (bit-identical; constant divides via 2-FMA) ----
        float xs = divc(T - 340.0f, DC(5.0));
        float s  = 1.0f / (1.0f + expf(-xs));
        float a  = (1.0f - s) * LOG_R_INS;
        float G  = expf(-a);
        float I  = v * G;

        float vn = v + divc(10.0f * (divc(Vd - v, DC(12.0)) - I), DC(100.0));
        float q  = (v * I - (T - 325.0f)) + 0.02f * lap;
        float Tn = (T + divc(10.0f * q, DC(1000.0))) + nz;

        // ---- rising-edge peak detection, refractory 101 ----
        bool pk = (I > 1.5f) && (prevI <= 1.5f) && (cd <= 0);
        if (pk) { mask |= binbit; cd = 101; }
        else    { cd -= 1; }
        if (--c50 == 0) { c50 = 50; binbit <<= 1; }

        prevI = I; v = vn; T = Tn;
        nz = nz_next; p ^= 1;
    }

    // ---- readout ----
    float acc[NOUT];
#pragma unroll
    for (int o = 0; o < NOUT; ++o) acc[o] = 0.0f;
#pragma unroll
    for (int tb = 0; tb < LENTB; ++tb) {
        if ((mask >> tb) & 1u) {
            const float* wp = W + (n * LENTB + tb);
#pragma unroll
            for (int o = 0; o < NOUT; ++o) acc[o] += wp[o * FEATS];
        }
    }
#pragma unroll
    for (int o = 0; o < NOUT; ++o) {
        float a2 = acc[o];
#pragma unroll
        for (int sft = 16; sft > 0; sft >>= 1)
            a2 += __shfl_xor_sync(0xFFFFFFFFu, a2, sft);
        acc[o] = a2;
    }
    const int wid = n >> 5;
    if ((n & 31) == 0) {
#pragma unroll
        for (int o = 0; o < NOUT; ++o) red[wid * NOUT + o] = acc[o];
    }
    __syncthreads();

    if (n == 0) {
        float lg[NOUT];
#pragma unroll
        for (int o = 0; o < NOUT; ++o) {
            float sacc = bias[o];
            for (int w = 0; w < 32; ++w) sacc += red[w * NOUT + o];
            lg[o] = sacc;
        }
        float m = lg[0];
#pragma unroll
        for (int o = 1; o < NOUT; ++o) m = fmaxf(m, lg[o]);
        float se = 0.0f;
#pragma unroll
        for (int o = 0; o < NOUT; ++o) se += expf(lg[o] - m);
        float lse = logf(se);
#pragma unroll
        for (int o = 0; o < NOUT; ++o) out[b * NOUT + o] = (lg[o] - m) - lse;
    }
}

extern "C" void kernel_launch(void* const* d_in, const int* in_sizes, int n_in,
                              void* d_out, int out_size) {
    const float* x    = (const float*)d_in[0];
    const float* W    = (const float*)d_in[1];
    const float* bias = (const float*)d_in[2];
    float* out = (float*)d_out;
    reset_cnt_kernel<<<1, 64>>>();
    Reservoir2D_kernel<<<TOTAL_CTAS, NN>>>(x, W, bias, out);
}